// round 1
// baseline (speedup 1.0000x reference)
#include <cuda_runtime.h>
#include <cuda_bf16.h>

#define N_NODES 50000
#define N_EDGES 800000
#define D 128
#define N_GRAPHS 128
#define LN_EPS 1e-5f

// -------------------- device scratch (no allocations allowed) --------------------
__device__ float g_t[N_NODES * D];       // GEMM output (messages pre-aggregation)
__device__ float g_h[N_NODES * D];       // node state
__device__ int   g_cnt[N_NODES];         // dst histogram
__device__ float g_dinv[N_NODES];        // 1/sqrt(deg)
__device__ int   g_rowoff[N_NODES + 1];  // CSR row offsets (by dst)
__device__ int   g_cursor[N_NODES];      // CSR fill cursors
__device__ int   g_srcs[N_EDGES];        // CSR column (src node id)
__device__ float g_y[N_GRAPHS * D];      // pooled per-graph features

// -------------------- CSR build --------------------
__global__ void zero_cnt_kernel() {
    int i = blockIdx.x * blockDim.x + threadIdx.x;
    if (i < N_NODES) g_cnt[i] = 0;
}

__global__ void count_kernel(const int* __restrict__ edge_index) {
    int e = blockIdx.x * blockDim.x + threadIdx.x;
    if (e < N_EDGES) {
        int d = edge_index[N_EDGES + e];  // dst row
        atomicAdd(&g_cnt[d], 1);
    }
}

// single-block exclusive scan over g_cnt -> g_rowoff, plus dinv & cursor init
__global__ void scan_kernel() {
    __shared__ int psum[1024];
    int t = threadIdx.x;
    const int CH = (N_NODES + 1023) / 1024;  // 49
    int base = t * CH;
    int s = 0;
    for (int i = 0; i < CH; i++) {
        int idx = base + i;
        if (idx < N_NODES) s += g_cnt[idx];
    }
    psum[t] = s;
    __syncthreads();
    // Hillis-Steele inclusive scan
    for (int o = 1; o < 1024; o <<= 1) {
        int v = 0;
        if (t >= o) v = psum[t - o];
        __syncthreads();
        psum[t] += v;
        __syncthreads();
    }
    int run = (t == 0) ? 0 : psum[t - 1];
    for (int i = 0; i < CH; i++) {
        int idx = base + i;
        if (idx < N_NODES) {
            int c = g_cnt[idx];
            g_rowoff[idx] = run;
            run += c;
            g_cursor[idx] = 0;
            g_dinv[idx] = rsqrtf((float)(c + 1));  // +1: self-loop
        }
    }
    if (t == 1023) g_rowoff[N_NODES] = psum[1023];
}

__global__ void fill_kernel(const int* __restrict__ edge_index) {
    int e = blockIdx.x * blockDim.x + threadIdx.x;
    if (e < N_EDGES) {
        int s = edge_index[e];
        int d = edge_index[N_EDGES + e];
        int pos = g_rowoff[d] + atomicAdd(&g_cursor[d], 1);
        g_srcs[pos] = s;
    }
}

// -------------------- GEMM: g_t = A[nrows x 128] @ W[128 x 128] --------------------
// Block: 256 threads, tile 64 rows x 128 cols, 8x4 micro-tile per thread.
// Warp layout: tc = tid&31 (col group), tr = tid>>5 (row group) -> A reads are
// warp-uniform broadcasts (conflict-free), B reads are float4 coalesced.
#define BM 64
#define APAD 132

__global__ void __launch_bounds__(256) gemm_kernel(const float* __restrict__ A,
                                                   const float* __restrict__ W) {
    extern __shared__ float sm[];
    float* As = sm;                 // [BM][APAD]
    float* Ws = sm + BM * APAD;     // [128][128]
    int tid = threadIdx.x;
    int r0 = blockIdx.x * BM;

    // load W (16384 floats -> 4096 float4 -> 16/thread)
    {
        const float4* W4 = (const float4*)W;
        float4* Ws4 = (float4*)Ws;
#pragma unroll
        for (int i = 0; i < 16; i++) Ws4[tid + i * 256] = W4[tid + i * 256];
    }
    // load A tile (64x128 = 2048 float4 -> 8/thread)
    {
        const float4* A4 = (const float4*)A;
#pragma unroll
        for (int i = 0; i < 8; i++) {
            int idx = tid + i * 256;     // float4 index within tile
            int row = idx >> 5;          // 32 float4 per row
            int k4 = idx & 31;
            float4 v = make_float4(0.f, 0.f, 0.f, 0.f);
            if (r0 + row < N_NODES) v = A4[(r0 + row) * 32 + k4];
            float* dp = &As[row * APAD + k4 * 4];
            dp[0] = v.x; dp[1] = v.y; dp[2] = v.z; dp[3] = v.w;
        }
    }
    __syncthreads();

    int tc = tid & 31;
    int tr = tid >> 5;
    float acc[8][4];
#pragma unroll
    for (int i = 0; i < 8; i++)
#pragma unroll
        for (int j = 0; j < 4; j++) acc[i][j] = 0.f;

#pragma unroll 4
    for (int k = 0; k < 128; k++) {
        float4 b = ((const float4*)(Ws + k * 128))[tc];
        float a[8];
#pragma unroll
        for (int i = 0; i < 8; i++) a[i] = As[(tr * 8 + i) * APAD + k];
#pragma unroll
        for (int i = 0; i < 8; i++) {
            acc[i][0] += a[i] * b.x;
            acc[i][1] += a[i] * b.y;
            acc[i][2] += a[i] * b.z;
            acc[i][3] += a[i] * b.w;
        }
    }

    float4* T4 = (float4*)g_t;
#pragma unroll
    for (int i = 0; i < 8; i++) {
        int row = r0 + tr * 8 + i;
        if (row < N_NODES) {
            float4 v = make_float4(acc[i][0], acc[i][1], acc[i][2], acc[i][3]);
            T4[row * 32 + tc] = v;
        }
    }
}

// -------------------- aggregation (+optional bias/LN/ReLU/residual fused) --------------------
// one warp per node; lane owns 4 feature channels (float4)
__global__ void __launch_bounds__(256) agg_kernel(const float* __restrict__ bias,
                                                  const float* __restrict__ gamma,
                                                  const float* __restrict__ beta,
                                                  int mode /*0=plain write, 1=LN+relu+residual*/) {
    int gw = (blockIdx.x * blockDim.x + threadIdx.x) >> 5;
    int lane = threadIdx.x & 31;
    if (gw >= N_NODES) return;
    int n = gw;

    float dn = g_dinv[n];
    const float4* T4 = (const float4*)g_t;

    // self loop: weight dinv[n]^2
    float4 tv = T4[n * 32 + lane];
    float w0 = dn * dn;
    float ax = tv.x * w0, ay = tv.y * w0, az = tv.z * w0, aw = tv.w * w0;

    int e0 = g_rowoff[n];
    int e1 = g_rowoff[n + 1];
    for (int e = e0; e < e1; e++) {
        int s = g_srcs[e];                 // broadcast across warp
        float w = g_dinv[s] * dn;
        float4 sv = T4[s * 32 + lane];
        ax += sv.x * w; ay += sv.y * w; az += sv.z * w; aw += sv.w * w;
    }

    float4 bv = ((const float4*)bias)[lane];
    ax += bv.x; ay += bv.y; az += bv.z; aw += bv.w;

    float4* H4 = (float4*)g_h;
    if (mode == 0) {
        H4[n * 32 + lane] = make_float4(ax, ay, az, aw);
    } else {
        // LayerNorm over 128 channels (population variance)
        float s1 = ax + ay + az + aw;
        float s2 = ax * ax + ay * ay + az * az + aw * aw;
#pragma unroll
        for (int o = 16; o > 0; o >>= 1) {
            s1 += __shfl_xor_sync(0xffffffffu, s1, o);
            s2 += __shfl_xor_sync(0xffffffffu, s2, o);
        }
        float mu = s1 * (1.f / 128.f);
        float var = s2 * (1.f / 128.f) - mu * mu;
        float rs = rsqrtf(var + LN_EPS);
        float4 gv = ((const float4*)gamma)[lane];
        float4 bev = ((const float4*)beta)[lane];
        float4 hv = H4[n * 32 + lane];
        float rx = fmaxf((ax - mu) * rs * gv.x + bev.x, 0.f);
        float ry = fmaxf((ay - mu) * rs * gv.y + bev.y, 0.f);
        float rz = fmaxf((az - mu) * rs * gv.z + bev.z, 0.f);
        float rw = fmaxf((aw - mu) * rs * gv.w + bev.w, 0.f);
        H4[n * 32 + lane] = make_float4(hv.x + rx, hv.y + ry, hv.z + rz, hv.w + rw);
    }
}

// -------------------- pooling + readout --------------------
__global__ void zero_y_kernel() {
    int i = blockIdx.x * blockDim.x + threadIdx.x;
    if (i < N_GRAPHS * D) g_y[i] = 0.f;
}

__global__ void pool_kernel(const int* __restrict__ batch_idx) {
    int i = blockIdx.x * blockDim.x + threadIdx.x;  // over N_NODES*32 float4 slots
    if (i >= N_NODES * 32) return;
    int n = i >> 5, lane = i & 31;
    float4 v = ((const float4*)g_h)[i];
    int g = batch_idx[n];
    float* yp = g_y + g * D + lane * 4;
    atomicAdd(yp + 0, v.x);
    atomicAdd(yp + 1, v.y);
    atomicAdd(yp + 2, v.z);
    atomicAdd(yp + 3, v.w);
}

__global__ void readout_kernel(const float* __restrict__ W1, const float* __restrict__ b1,
                               const float* __restrict__ W2, const float* __restrict__ b2,
                               float* __restrict__ out) {
    __shared__ float yrow[128];
    __shared__ float partial[4];
    int g = blockIdx.x, j = threadIdx.x;
    yrow[j] = g_y[g * D + j];
    __syncthreads();
    float acc = 0.f;
#pragma unroll 8
    for (int k = 0; k < 128; k++) acc += yrow[k] * W1[k * D + j];
    float z = fmaxf(acc + b1[j], 0.f);
    float p = z * W2[j];
#pragma unroll
    for (int o = 16; o > 0; o >>= 1) p += __shfl_xor_sync(0xffffffffu, p, o);
    if ((j & 31) == 0) partial[j >> 5] = p;
    __syncthreads();
    if (j == 0) out[g] = partial[0] + partial[1] + partial[2] + partial[3] + b2[0];
}

// -------------------- launch --------------------
extern "C" void kernel_launch(void* const* d_in, const int* in_sizes, int n_in,
                              void* d_out, int out_size) {
    const float* x      = (const float*)d_in[0];
    const int*   ei     = (const int*)d_in[1];
    const int*   batch  = (const int*)d_in[2];
    const float* W_enc  = (const float*)d_in[3];
    const float* b_enc  = (const float*)d_in[4];
    const float* W_blk  = (const float*)d_in[5];
    const float* b_blk  = (const float*)d_in[6];
    const float* gamma  = (const float*)d_in[7];
    const float* beta   = (const float*)d_in[8];
    const float* W1     = (const float*)d_in[9];
    const float* b1     = (const float*)d_in[10];
    const float* W2     = (const float*)d_in[11];
    const float* b2     = (const float*)d_in[12];
    float* out = (float*)d_out;

    float* dh = nullptr;
    cudaGetSymbolAddress((void**)&dh, g_h);

    const int smem_gemm = BM * APAD * 4 + 128 * 128 * 4;  // 99328 B
    cudaFuncSetAttribute(gemm_kernel, cudaFuncAttributeMaxDynamicSharedMemorySize, smem_gemm);

    const int TB = 256;
    int nblk_nodes = (N_NODES + TB - 1) / TB;
    int nblk_edges = (N_EDGES + TB - 1) / TB;
    int nblk_gemm  = (N_NODES + BM - 1) / BM;
    int nblk_agg   = (N_NODES * 32 + TB - 1) / TB;

    // CSR build
    zero_cnt_kernel<<<nblk_nodes, TB>>>();
    count_kernel<<<nblk_edges, TB>>>(ei);
    scan_kernel<<<1, 1024>>>();
    fill_kernel<<<nblk_edges, TB>>>(ei);

    // encoder: h = gcn(x, W_enc, b_enc)
    gemm_kernel<<<nblk_gemm, TB, smem_gemm>>>(x, W_enc);
    agg_kernel<<<nblk_agg, TB>>>(b_enc, nullptr, nullptr, 0);

    // standalone blk0: h = gcn(h, W_blk[0], b_blk[0])
    gemm_kernel<<<nblk_gemm, TB, smem_gemm>>>(dh, W_blk + 0 * D * D);
    agg_kernel<<<nblk_agg, TB>>>(b_blk + 0 * D, nullptr, nullptr, 0);

    // res blocks l = 0,1,2: h = h + relu(LN(gcn(h, W_blk[l], b_blk[l])))
    for (int l = 0; l < 3; l++) {
        gemm_kernel<<<nblk_gemm, TB, smem_gemm>>>(dh, W_blk + l * D * D);
        agg_kernel<<<nblk_agg, TB>>>(b_blk + l * D, gamma + l * D, beta + l * D, 1);
    }

    // pool + readout
    zero_y_kernel<<<(N_GRAPHS * D + TB - 1) / TB, TB>>>();
    pool_kernel<<<nblk_agg, TB>>>(batch);
    readout_kernel<<<N_GRAPHS, 128>>>(W1, b1, W2, b2, out);
}

// round 3
// speedup vs baseline: 1.4427x; 1.4427x over previous
#include <cuda_runtime.h>
#include <cuda_bf16.h>
#include <cstdint>

#define N_NODES 50000
#define N_EDGES 800000
#define D 128
#define N_GRAPHS 128
#define LN_EPS 1e-5f

// ==================== device scratch ====================
__device__ float g_t[N_NODES * D];       // GEMM output (pre-aggregation messages)
__device__ float g_h[N_NODES * D];       // node state
__device__ int   g_cnt[N_NODES];
__device__ float g_dinv[N_NODES];
__device__ int   g_rowoff[N_NODES + 1];
__device__ int   g_cursor[N_NODES];
__device__ int   g_srcs[N_EDGES];
__device__ float g_y[N_GRAPHS * D];
__device__ float g_wt[D * D];            // W^T, tf32-rounded, n-major [n][k]

__device__ __forceinline__ float tf32r(float v) {
    uint32_t t;
    asm("cvt.rna.tf32.f32 %0, %1;" : "=r"(t) : "f"(v));
    return __uint_as_float(t);
}

// ==================== CSR build ====================
__global__ void zero_cnt_kernel() {
    int i = blockIdx.x * blockDim.x + threadIdx.x;
    if (i < N_NODES) g_cnt[i] = 0;
}

__global__ void count_kernel(const int* __restrict__ edge_index) {
    int e = blockIdx.x * blockDim.x + threadIdx.x;
    if (e < N_EDGES) atomicAdd(&g_cnt[edge_index[N_EDGES + e]], 1);
}

__global__ void scan_kernel() {
    __shared__ int psum[1024];
    int t = threadIdx.x;
    const int CH = (N_NODES + 1023) / 1024;
    int base = t * CH, s = 0;
    for (int i = 0; i < CH; i++) {
        int idx = base + i;
        if (idx < N_NODES) s += g_cnt[idx];
    }
    psum[t] = s;
    __syncthreads();
    for (int o = 1; o < 1024; o <<= 1) {
        int v = 0;
        if (t >= o) v = psum[t - o];
        __syncthreads();
        psum[t] += v;
        __syncthreads();
    }
    int run = (t == 0) ? 0 : psum[t - 1];
    for (int i = 0; i < CH; i++) {
        int idx = base + i;
        if (idx < N_NODES) {
            int c = g_cnt[idx];
            g_rowoff[idx] = run;
            run += c;
            g_cursor[idx] = 0;
            g_dinv[idx] = rsqrtf((float)(c + 1));
        }
    }
    if (t == 1023) g_rowoff[N_NODES] = psum[1023];
}

__global__ void fill_kernel(const int* __restrict__ edge_index) {
    int e = blockIdx.x * blockDim.x + threadIdx.x;
    if (e < N_EDGES) {
        int s = edge_index[e];
        int d = edge_index[N_EDGES + e];
        int pos = g_rowoff[d] + atomicAdd(&g_cursor[d], 1);
        g_srcs[pos] = s;
    }
}

// ==================== W prep: transpose + tf32 round ====================
__global__ void prep_w_kernel(const float* __restrict__ W) {
    int idx = blockIdx.x * blockDim.x + threadIdx.x;  // idx = k*128+n
    int n = idx & 127, k = idx >> 7;
    g_wt[n * D + k] = tf32r(W[idx]);
}

// ==================== tensor-core GEMM via mma.sync (tf32) ====================
// C[128x128] per CTA, K=128 resident in smem. 8 warps: 2(M) x 4(N),
// warp tile 64x32 = 4x4 m16n8k8 fragments.
#define PAD 132

__global__ void __launch_bounds__(256) gemm_mma_kernel(const float* __restrict__ A) {
    extern __shared__ float sm[];
    float* As = sm;               // [128][PAD] row-major (m, k)
    float* Bs = sm + 128 * PAD;   // [128][PAD] n-major (n, k)  == W^T
    int tid = threadIdx.x;
    int r0 = blockIdx.x * 128;

    // stage B = W^T (already tf32-rounded)
    {
        const float4* w4 = (const float4*)g_wt;
#pragma unroll
        for (int i = 0; i < 16; i++) {
            int idx = tid + i * 256;           // 4096 float4
            int n = idx >> 5, k4 = idx & 31;
            *(float4*)&Bs[n * PAD + k4 * 4] = w4[idx];
        }
    }
    // stage A (tf32-round on the fly)
    {
        const float4* A4 = (const float4*)A;
#pragma unroll
        for (int i = 0; i < 16; i++) {
            int idx = tid + i * 256;
            int m = idx >> 5, k4 = idx & 31;
            float4 v = make_float4(0.f, 0.f, 0.f, 0.f);
            if (r0 + m < N_NODES) v = A4[(r0 + m) * 32 + k4];
            v.x = tf32r(v.x); v.y = tf32r(v.y); v.z = tf32r(v.z); v.w = tf32r(v.w);
            *(float4*)&As[m * PAD + k4 * 4] = v;
        }
    }
    __syncthreads();

    int lane = tid & 31, wid = tid >> 5;
    int wm = (wid & 1) * 64;      // warp M offset
    int wn = (wid >> 1) * 32;     // warp N offset
    int gq = lane >> 2, tq = lane & 3;

    float acc[4][4][4];
#pragma unroll
    for (int mf = 0; mf < 4; mf++)
#pragma unroll
        for (int nf = 0; nf < 4; nf++)
#pragma unroll
            for (int j = 0; j < 4; j++) acc[mf][nf][j] = 0.f;

#pragma unroll
    for (int k0 = 0; k0 < 128; k0 += 8) {
        uint32_t a[4][4];
#pragma unroll
        for (int mf = 0; mf < 4; mf++) {
            const float* ap = &As[(wm + mf * 16 + gq) * PAD + k0 + tq];
            a[mf][0] = __float_as_uint(ap[0]);
            a[mf][2] = __float_as_uint(ap[4]);
            a[mf][1] = __float_as_uint(ap[8 * PAD]);
            a[mf][3] = __float_as_uint(ap[8 * PAD + 4]);
        }
        uint32_t b[4][2];
#pragma unroll
        for (int nf = 0; nf < 4; nf++) {
            const float* bp = &Bs[(wn + nf * 8 + gq) * PAD + k0 + tq];
            b[nf][0] = __float_as_uint(bp[0]);
            b[nf][1] = __float_as_uint(bp[4]);
        }
#pragma unroll
        for (int mf = 0; mf < 4; mf++)
#pragma unroll
            for (int nf = 0; nf < 4; nf++) {
                asm volatile(
                    "mma.sync.aligned.m16n8k8.row.col.f32.tf32.tf32.f32 "
                    "{%0,%1,%2,%3}, {%4,%5,%6,%7}, {%8,%9}, {%0,%1,%2,%3};"
                    : "+f"(acc[mf][nf][0]), "+f"(acc[mf][nf][1]),
                      "+f"(acc[mf][nf][2]), "+f"(acc[mf][nf][3])
                    : "r"(a[mf][0]), "r"(a[mf][1]), "r"(a[mf][2]), "r"(a[mf][3]),
                      "r"(b[nf][0]), "r"(b[nf][1]));
            }
    }

    // epilogue: write to g_t
#pragma unroll
    for (int mf = 0; mf < 4; mf++) {
        int row0 = r0 + wm + mf * 16 + gq;
#pragma unroll
        for (int nf = 0; nf < 4; nf++) {
            int col = wn + nf * 8 + 2 * tq;
            if (row0 < N_NODES)
                *(float2*)(g_t + (size_t)row0 * D + col) = make_float2(acc[mf][nf][0], acc[mf][nf][1]);
            if (row0 + 8 < N_NODES)
                *(float2*)(g_t + (size_t)(row0 + 8) * D + col) = make_float2(acc[mf][nf][2], acc[mf][nf][3]);
        }
    }
}

// ==================== aggregation (+bias / LN+ReLU+residual fused) ====================
__global__ void __launch_bounds__(256) agg_kernel(const float* __restrict__ bias,
                                                  const float* __restrict__ gamma,
                                                  const float* __restrict__ beta,
                                                  int mode) {
    int gw = (blockIdx.x * blockDim.x + threadIdx.x) >> 5;
    int lane = threadIdx.x & 31;
    if (gw >= N_NODES) return;
    int n = gw;

    float dn = g_dinv[n];
    const float4* T4 = (const float4*)g_t;

    float4 tv = T4[n * 32 + lane];
    float w0 = dn * dn;
    float ax = tv.x * w0, ay = tv.y * w0, az = tv.z * w0, aw = tv.w * w0;

    int e0 = g_rowoff[n], e1 = g_rowoff[n + 1];
    for (int e = e0; e < e1; e++) {
        int s = g_srcs[e];
        float w = g_dinv[s] * dn;
        float4 sv = T4[s * 32 + lane];
        ax += sv.x * w; ay += sv.y * w; az += sv.z * w; aw += sv.w * w;
    }

    float4 bv = ((const float4*)bias)[lane];
    ax += bv.x; ay += bv.y; az += bv.z; aw += bv.w;

    float4* H4 = (float4*)g_h;
    if (mode == 0) {
        H4[n * 32 + lane] = make_float4(ax, ay, az, aw);
    } else {
        float s1 = ax + ay + az + aw;
        float s2 = ax * ax + ay * ay + az * az + aw * aw;
#pragma unroll
        for (int o = 16; o > 0; o >>= 1) {
            s1 += __shfl_xor_sync(0xffffffffu, s1, o);
            s2 += __shfl_xor_sync(0xffffffffu, s2, o);
        }
        float mu = s1 * (1.f / 128.f);
        float var = s2 * (1.f / 128.f) - mu * mu;
        float rs = rsqrtf(var + LN_EPS);
        float4 gv = ((const float4*)gamma)[lane];
        float4 bev = ((const float4*)beta)[lane];
        float4 hv = H4[n * 32 + lane];
        float rx = fmaxf((ax - mu) * rs * gv.x + bev.x, 0.f);
        float ry = fmaxf((ay - mu) * rs * gv.y + bev.y, 0.f);
        float rz = fmaxf((az - mu) * rs * gv.z + bev.z, 0.f);
        float rw = fmaxf((aw - mu) * rs * gv.w + bev.w, 0.f);
        H4[n * 32 + lane] = make_float4(hv.x + rx, hv.y + ry, hv.z + rz, hv.w + rw);
    }
}

// ==================== pooling + readout ====================
__global__ void zero_y_kernel() {
    int i = blockIdx.x * blockDim.x + threadIdx.x;
    if (i < N_GRAPHS * D) g_y[i] = 0.f;
}

// 8 consecutive nodes per warp iteration; batch_idx sorted -> few atomics
__global__ void pool_kernel(const int* __restrict__ batch_idx) {
    int t = blockIdx.x * blockDim.x + threadIdx.x;
    int lane = t & 31;
    int n0 = (t >> 5) * 8;
    if (n0 >= N_NODES) return;
    const float4* H4 = (const float4*)g_h;
    float4 acc = make_float4(0.f, 0.f, 0.f, 0.f);
    int cur = batch_idx[n0];
    int nend = n0 + 8;
    if (nend > N_NODES) nend = N_NODES;
    for (int n = n0; n < nend; n++) {
        int b = batch_idx[n];
        if (b != cur) {
            float* yp = g_y + cur * D + lane * 4;
            atomicAdd(yp + 0, acc.x); atomicAdd(yp + 1, acc.y);
            atomicAdd(yp + 2, acc.z); atomicAdd(yp + 3, acc.w);
            acc = make_float4(0.f, 0.f, 0.f, 0.f);
            cur = b;
        }
        float4 v = H4[n * 32 + lane];
        acc.x += v.x; acc.y += v.y; acc.z += v.z; acc.w += v.w;
    }
    float* yp = g_y + cur * D + lane * 4;
    atomicAdd(yp + 0, acc.x); atomicAdd(yp + 1, acc.y);
    atomicAdd(yp + 2, acc.z); atomicAdd(yp + 3, acc.w);
}

__global__ void readout_kernel(const float* __restrict__ W1, const float* __restrict__ b1,
                               const float* __restrict__ W2, const float* __restrict__ b2,
                               float* __restrict__ out) {
    __shared__ float yrow[128];
    __shared__ float partial[4];
    int g = blockIdx.x, j = threadIdx.x;
    yrow[j] = g_y[g * D + j];
    __syncthreads();
    float acc = 0.f;
#pragma unroll 8
    for (int k = 0; k < 128; k++) acc += yrow[k] * W1[k * D + j];
    float z = fmaxf(acc + b1[j], 0.f);
    float p = z * W2[j];
#pragma unroll
    for (int o = 16; o > 0; o >>= 1) p += __shfl_xor_sync(0xffffffffu, p, o);
    if ((j & 31) == 0) partial[j >> 5] = p;
    __syncthreads();
    if (j == 0) out[g] = partial[0] + partial[1] + partial[2] + partial[3] + b2[0];
}

// ==================== launch ====================
extern "C" void kernel_launch(void* const* d_in, const int* in_sizes, int n_in,
                              void* d_out, int out_size) {
    const float* x      = (const float*)d_in[0];
    const int*   ei     = (const int*)d_in[1];
    const int*   batch  = (const int*)d_in[2];
    const float* W_enc  = (const float*)d_in[3];
    const float* b_enc  = (const float*)d_in[4];
    const float* W_blk  = (const float*)d_in[5];
    const float* b_blk  = (const float*)d_in[6];
    const float* gamma  = (const float*)d_in[7];
    const float* beta   = (const float*)d_in[8];
    const float* W1     = (const float*)d_in[9];
    const float* b1     = (const float*)d_in[10];
    const float* W2     = (const float*)d_in[11];
    const float* b2     = (const float*)d_in[12];
    float* out = (float*)d_out;

    float* dh = nullptr;
    cudaGetSymbolAddress((void**)&dh, g_h);

    const int smem_gemm = 2 * 128 * PAD * 4;  // 135168 B
    cudaFuncSetAttribute(gemm_mma_kernel, cudaFuncAttributeMaxDynamicSharedMemorySize, smem_gemm);

    const int TB = 256;
    int nblk_nodes = (N_NODES + TB - 1) / TB;
    int nblk_edges = (N_EDGES + TB - 1) / TB;
    int nblk_gemm  = (N_NODES + 127) / 128;
    int nblk_agg   = (N_NODES * 32 + TB - 1) / TB;

    // CSR build
    zero_cnt_kernel<<<nblk_nodes, TB>>>();
    count_kernel<<<nblk_edges, TB>>>(ei);
    scan_kernel<<<1, 1024>>>();
    fill_kernel<<<nblk_edges, TB>>>(ei);

    // encoder
    prep_w_kernel<<<64, TB>>>(W_enc);
    gemm_mma_kernel<<<nblk_gemm, TB, smem_gemm>>>(x);
    agg_kernel<<<nblk_agg, TB>>>(b_enc, nullptr, nullptr, 0);

    // standalone blk0
    prep_w_kernel<<<64, TB>>>(W_blk + 0 * D * D);
    gemm_mma_kernel<<<nblk_gemm, TB, smem_gemm>>>(dh);
    agg_kernel<<<nblk_agg, TB>>>(b_blk + 0 * D, nullptr, nullptr, 0);

    // res blocks
    for (int l = 0; l < 3; l++) {
        prep_w_kernel<<<64, TB>>>(W_blk + l * D * D);
        gemm_mma_kernel<<<nblk_gemm, TB, smem_gemm>>>(dh);
        agg_kernel<<<nblk_agg, TB>>>(b_blk + l * D, gamma + l * D, beta + l * D, 1);
    }

    // pool + readout
    zero_y_kernel<<<(N_GRAPHS * D + TB - 1) / TB, TB>>>();
    pool_kernel<<<((N_NODES + 7) / 8 * 32 + TB - 1) / TB, TB>>>(batch);
    readout_kernel<<<N_GRAPHS, 128>>>(W1, b1, W2, b2, out);
}

// round 5
// speedup vs baseline: 1.4760x; 1.0231x over previous
#include <cuda_runtime.h>
#include <cuda_fp16.h>
#include <cstdint>

#define N_NODES 50000
#define N_EDGES 800000
#define D 128
#define N_GRAPHS 128
#define LN_EPS 1e-5f

// ==================== device scratch ====================
__device__ uint2 g_t2[N_NODES * 32];     // messages, fp16: 128 ch = 32 x uint2 per node
__device__ float g_h[N_NODES * D];       // node state (fp32)
__device__ int   g_cnt[N_NODES];
__device__ float g_dinv[N_NODES];
__device__ int   g_rowoff[N_NODES + 1];
__device__ int   g_cursor[N_NODES];
__device__ int   g_srcs[N_EDGES];
__device__ float g_y[N_GRAPHS * D];

__device__ __forceinline__ float tf32r(float v) {
    uint32_t t;
    asm("cvt.rna.tf32.f32 %0, %1;" : "=r"(t) : "f"(v));
    return __uint_as_float(t);
}

__device__ __forceinline__ uint32_t pack_h2(float a, float b) {
    __half2 h = __floats2half2_rn(a, b);
    return *reinterpret_cast<uint32_t*>(&h);
}

// ==================== CSR build ====================
__global__ void zero_cnt_kernel() {
    int i = blockIdx.x * blockDim.x + threadIdx.x;
    if (i < N_NODES) g_cnt[i] = 0;
}

// 4 edges per thread: MLP=4 on loads + atomics (atomic-latency-bound kernel)
__global__ void count_kernel(const int* __restrict__ edge_index) {
    int e = (blockIdx.x * blockDim.x + threadIdx.x) * 4;
    if (e >= N_EDGES) return;
    int4 d = *(const int4*)(edge_index + N_EDGES + e);
    atomicAdd(&g_cnt[d.x], 1);
    atomicAdd(&g_cnt[d.y], 1);
    atomicAdd(&g_cnt[d.z], 1);
    atomicAdd(&g_cnt[d.w], 1);
}

__global__ void scan_kernel() {
    __shared__ int psum[1024];
    int t = threadIdx.x;
    const int CH = (N_NODES + 1023) / 1024;
    int base = t * CH, s = 0;
    for (int i = 0; i < CH; i++) {
        int idx = base + i;
        if (idx < N_NODES) s += g_cnt[idx];
    }
    psum[t] = s;
    __syncthreads();
    for (int o = 1; o < 1024; o <<= 1) {
        int v = 0;
        if (t >= o) v = psum[t - o];
        __syncthreads();
        psum[t] += v;
        __syncthreads();
    }
    int run = (t == 0) ? 0 : psum[t - 1];
    for (int i = 0; i < CH; i++) {
        int idx = base + i;
        if (idx < N_NODES) {
            int c = g_cnt[idx];
            g_rowoff[idx] = run;
            run += c;
            g_cursor[idx] = 0;
            g_dinv[idx] = rsqrtf((float)(c + 1));
        }
    }
    if (t == 1023) g_rowoff[N_NODES] = psum[1023];
}

__global__ void fill_kernel(const int* __restrict__ edge_index) {
    int e = (blockIdx.x * blockDim.x + threadIdx.x) * 4;
    if (e >= N_EDGES) return;
    int4 s = *(const int4*)(edge_index + e);
    int4 d = *(const int4*)(edge_index + N_EDGES + e);
    int p0 = g_rowoff[d.x] + atomicAdd(&g_cursor[d.x], 1);
    int p1 = g_rowoff[d.y] + atomicAdd(&g_cursor[d.y], 1);
    int p2 = g_rowoff[d.z] + atomicAdd(&g_cursor[d.z], 1);
    int p3 = g_rowoff[d.w] + atomicAdd(&g_cursor[d.w], 1);
    g_srcs[p0] = s.x;
    g_srcs[p1] = s.y;
    g_srcs[p2] = s.z;
    g_srcs[p3] = s.w;
}

// ==================== tensor-core GEMM via mma.sync (tf32) ====================
// C[128x128] per CTA, K=128 resident. 8 warps: 2(M) x 4(N), warp tile 64x32.
// W transposed + tf32-rounded in-kernel; output written fp16 to g_t2.
#define PAD 132

__global__ void __launch_bounds__(256) gemm_mma_kernel(const float* __restrict__ A,
                                                       const float* __restrict__ W) {
    extern __shared__ float sm[];
    float* As = sm;               // [128][PAD] (m, k)
    float* Bs = sm + 128 * PAD;   // [128][PAD] (n, k)  == W^T
    int tid = threadIdx.x;
    int r0 = blockIdx.x * 128;

    // stage B = W^T with tf32 round (coalesced read; write conflicts once per CTA = noise)
    {
#pragma unroll
        for (int i = 0; i < 64; i++) {
            int idx = tid + i * 256;          // idx = k*128 + n
            int n = idx & 127, k = idx >> 7;
            Bs[n * PAD + k] = tf32r(W[idx]);
        }
    }
    // stage A (tf32-round on the fly)
    {
        const float4* A4 = (const float4*)A;
#pragma unroll
        for (int i = 0; i < 16; i++) {
            int idx = tid + i * 256;
            int m = idx >> 5, k4 = idx & 31;
            float4 v = make_float4(0.f, 0.f, 0.f, 0.f);
            if (r0 + m < N_NODES) v = A4[(r0 + m) * 32 + k4];
            v.x = tf32r(v.x); v.y = tf32r(v.y); v.z = tf32r(v.z); v.w = tf32r(v.w);
            *(float4*)&As[m * PAD + k4 * 4] = v;
        }
    }
    __syncthreads();

    int lane = tid & 31, wid = tid >> 5;
    int wm = (wid & 1) * 64;
    int wn = (wid >> 1) * 32;
    int gq = lane >> 2, tq = lane & 3;

    float acc[4][4][4];
#pragma unroll
    for (int mf = 0; mf < 4; mf++)
#pragma unroll
        for (int nf = 0; nf < 4; nf++)
#pragma unroll
            for (int j = 0; j < 4; j++) acc[mf][nf][j] = 0.f;

#pragma unroll
    for (int k0 = 0; k0 < 128; k0 += 8) {
        uint32_t a[4][4];
#pragma unroll
        for (int mf = 0; mf < 4; mf++) {
            const float* ap = &As[(wm + mf * 16 + gq) * PAD + k0 + tq];
            a[mf][0] = __float_as_uint(ap[0]);
            a[mf][2] = __float_as_uint(ap[4]);
            a[mf][1] = __float_as_uint(ap[8 * PAD]);
            a[mf][3] = __float_as_uint(ap[8 * PAD + 4]);
        }
        uint32_t b[4][2];
#pragma unroll
        for (int nf = 0; nf < 4; nf++) {
            const float* bp = &Bs[(wn + nf * 8 + gq) * PAD + k0 + tq];
            b[nf][0] = __float_as_uint(bp[0]);
            b[nf][1] = __float_as_uint(bp[4]);
        }
#pragma unroll
        for (int mf = 0; mf < 4; mf++)
#pragma unroll
            for (int nf = 0; nf < 4; nf++) {
                asm volatile(
                    "mma.sync.aligned.m16n8k8.row.col.f32.tf32.tf32.f32 "
                    "{%0,%1,%2,%3}, {%4,%5,%6,%7}, {%8,%9}, {%0,%1,%2,%3};"
                    : "+f"(acc[mf][nf][0]), "+f"(acc[mf][nf][1]),
                      "+f"(acc[mf][nf][2]), "+f"(acc[mf][nf][3])
                    : "r"(a[mf][0]), "r"(a[mf][1]), "r"(a[mf][2]), "r"(a[mf][3]),
                      "r"(b[nf][0]), "r"(b[nf][1]));
            }
    }

    // epilogue: write fp16 messages
    uint32_t* T = (uint32_t*)g_t2;
#pragma unroll
    for (int mf = 0; mf < 4; mf++) {
        int row0 = r0 + wm + mf * 16 + gq;
#pragma unroll
        for (int nf = 0; nf < 4; nf++) {
            int c2 = (wn + nf * 8 + 2 * tq) >> 1;  // half2 index
            if (row0 < N_NODES)
                T[row0 * 64 + c2] = pack_h2(acc[mf][nf][0], acc[mf][nf][1]);
            if (row0 + 8 < N_NODES)
                T[(row0 + 8) * 64 + c2] = pack_h2(acc[mf][nf][2], acc[mf][nf][3]);
        }
    }
}

// ==================== aggregation (+bias / LN+ReLU+residual fused) ====================
// one warp per node; lane owns 4 channels (one uint2 = 2 half2)
__global__ void __launch_bounds__(256) agg_kernel(const float* __restrict__ bias,
                                                  const float* __restrict__ gamma,
                                                  const float* __restrict__ beta,
                                                  int mode) {
    int gw = (blockIdx.x * blockDim.x + threadIdx.x) >> 5;
    int lane = threadIdx.x & 31;
    if (gw >= N_NODES) return;
    int n = gw;

    float dn = g_dinv[n];

    uint2 raw = g_t2[(size_t)n * 32 + lane];
    float2 f0 = __half22float2(*reinterpret_cast<__half2*>(&raw.x));
    float2 f1 = __half22float2(*reinterpret_cast<__half2*>(&raw.y));
    float w0 = dn * dn;
    float ax = f0.x * w0, ay = f0.y * w0, az = f1.x * w0, aw = f1.y * w0;

    int e0 = g_rowoff[n], e1 = g_rowoff[n + 1];
    for (int e = e0; e < e1; e++) {
        int s = g_srcs[e];
        float w = g_dinv[s] * dn;
        uint2 r2 = g_t2[(size_t)s * 32 + lane];
        float2 s0 = __half22float2(*reinterpret_cast<__half2*>(&r2.x));
        float2 s1 = __half22float2(*reinterpret_cast<__half2*>(&r2.y));
        ax += s0.x * w; ay += s0.y * w; az += s1.x * w; aw += s1.y * w;
    }

    float4 bv = ((const float4*)bias)[lane];
    ax += bv.x; ay += bv.y; az += bv.z; aw += bv.w;

    float4* H4 = (float4*)g_h;
    if (mode == 0) {
        H4[n * 32 + lane] = make_float4(ax, ay, az, aw);
    } else {
        float s1 = ax + ay + az + aw;
        float s2 = ax * ax + ay * ay + az * az + aw * aw;
#pragma unroll
        for (int o = 16; o > 0; o >>= 1) {
            s1 += __shfl_xor_sync(0xffffffffu, s1, o);
            s2 += __shfl_xor_sync(0xffffffffu, s2, o);
        }
        float mu = s1 * (1.f / 128.f);
        float var = s2 * (1.f / 128.f) - mu * mu;
        float rs = rsqrtf(var + LN_EPS);
        float4 gv = ((const float4*)gamma)[lane];
        float4 bev = ((const float4*)beta)[lane];
        float4 hv = H4[n * 32 + lane];
        float rx = fmaxf((ax - mu) * rs * gv.x + bev.x, 0.f);
        float ry = fmaxf((ay - mu) * rs * gv.y + bev.y, 0.f);
        float rz = fmaxf((az - mu) * rs * gv.z + bev.z, 0.f);
        float rw = fmaxf((aw - mu) * rs * gv.w + bev.w, 0.f);
        H4[n * 32 + lane] = make_float4(hv.x + rx, hv.y + ry, hv.z + rz, hv.w + rw);
    }
}

// ==================== pooling + readout ====================
__global__ void zero_y_kernel() {
    int i = blockIdx.x * blockDim.x + threadIdx.x;
    if (i < N_GRAPHS * D) g_y[i] = 0.f;
}

__global__ void pool_kernel(const int* __restrict__ batch_idx) {
    int t = blockIdx.x * blockDim.x + threadIdx.x;
    int lane = t & 31;
    int n0 = (t >> 5) * 8;
    if (n0 >= N_NODES) return;
    const float4* H4 = (const float4*)g_h;
    float4 acc = make_float4(0.f, 0.f, 0.f, 0.f);
    int cur = batch_idx[n0];
    int nend = n0 + 8;
    if (nend > N_NODES) nend = N_NODES;
    for (int n = n0; n < nend; n++) {
        int b = batch_idx[n];
        if (b != cur) {
            float* yp = g_y + cur * D + lane * 4;
            atomicAdd(yp + 0, acc.x); atomicAdd(yp + 1, acc.y);
            atomicAdd(yp + 2, acc.z); atomicAdd(yp + 3, acc.w);
            acc = make_float4(0.f, 0.f, 0.f, 0.f);
            cur = b;
        }
        float4 v = H4[n * 32 + lane];
        acc.x += v.x; acc.y += v.y; acc.z += v.z; acc.w += v.w;
    }
    float* yp = g_y + cur * D + lane * 4;
    atomicAdd(yp + 0, acc.x); atomicAdd(yp + 1, acc.y);
    atomicAdd(yp + 2, acc.z); atomicAdd(yp + 3, acc.w);
}

__global__ void readout_kernel(const float* __restrict__ W1, const float* __restrict__ b1,
                               const float* __restrict__ W2, const float* __restrict__ b2,
                               float* __restrict__ out) {
    __shared__ float yrow[128];
    __shared__ float partial[4];
    int g = blockIdx.x, j = threadIdx.x;
    yrow[j] = g_y[g * D + j];
    __syncthreads();
    float acc = 0.f;
#pragma unroll 8
    for (int k = 0; k < 128; k++) acc += yrow[k] * W1[k * D + j];
    float z = fmaxf(acc + b1[j], 0.f);
    float p = z * W2[j];
#pragma unroll
    for (int o = 16; o > 0; o >>= 1) p += __shfl_xor_sync(0xffffffffu, p, o);
    if ((j & 31) == 0) partial[j >> 5] = p;
    __syncthreads();
    if (j == 0) out[g] = partial[0] + partial[1] + partial[2] + partial[3] + b2[0];
}

// ==================== launch ====================
extern "C" void kernel_launch(void* const* d_in, const int* in_sizes, int n_in,
                              void* d_out, int out_size) {
    const float* x      = (const float*)d_in[0];
    const int*   ei     = (const int*)d_in[1];
    const int*   batch  = (const int*)d_in[2];
    const float* W_enc  = (const float*)d_in[3];
    const float* b_enc  = (const float*)d_in[4];
    const float* W_blk  = (const float*)d_in[5];
    const float* b_blk  = (const float*)d_in[6];
    const float* gamma  = (const float*)d_in[7];
    const float* beta   = (const float*)d_in[8];
    const float* W1     = (const float*)d_in[9];
    const float* b1     = (const float*)d_in[10];
    const float* W2     = (const float*)d_in[11];
    const float* b2     = (const float*)d_in[12];
    float* out = (float*)d_out;

    float* dh = nullptr;
    cudaGetSymbolAddress((void**)&dh, g_h);

    const int smem_gemm = 2 * 128 * PAD * 4;  // 135168 B
    cudaFuncSetAttribute(gemm_mma_kernel, cudaFuncAttributeMaxDynamicSharedMemorySize, smem_gemm);

    const int TB = 256;
    int nblk_nodes = (N_NODES + TB - 1) / TB;
    int nblk_e4    = (N_EDGES / 4 + TB - 1) / TB;
    int nblk_gemm  = (N_NODES + 127) / 128;
    int nblk_agg   = (N_NODES * 32 + TB - 1) / TB;

    // CSR build
    zero_cnt_kernel<<<nblk_nodes, TB>>>();
    count_kernel<<<nblk_e4, TB>>>(ei);
    scan_kernel<<<1, 1024>>>();
    fill_kernel<<<nblk_e4, TB>>>(ei);

    // encoder
    gemm_mma_kernel<<<nblk_gemm, TB, smem_gemm>>>(x, W_enc);
    agg_kernel<<<nblk_agg, TB>>>(b_enc, nullptr, nullptr, 0);

    // standalone blk0
    gemm_mma_kernel<<<nblk_gemm, TB, smem_gemm>>>(dh, W_blk + 0 * D * D);
    agg_kernel<<<nblk_agg, TB>>>(b_blk + 0 * D, nullptr, nullptr, 0);

    // res blocks
    for (int l = 0; l < 3; l++) {
        gemm_mma_kernel<<<nblk_gemm, TB, smem_gemm>>>(dh, W_blk + l * D * D);
        agg_kernel<<<nblk_agg, TB>>>(b_blk + l * D, gamma + l * D, beta + l * D, 1);
    }

    // pool + readout
    zero_y_kernel<<<(N_GRAPHS * D + TB - 1) / TB, TB>>>();
    pool_kernel<<<((N_NODES + 7) / 8 * 32 + TB - 1) / TB, TB>>>(batch);
    readout_kernel<<<N_GRAPHS, 128>>>(W1, b1, W2, b2, out);
}